// round 13
// baseline (speedup 1.0000x reference)
#include <cuda_runtime.h>
#include <cuda_bf16.h>
#include <math.h>
#include <stdint.h>

#define Bsz   64
#define Lseq  512
#define Edim  10
#define Hdim  1900
#define Grows 7600
#define NOUT  25
#define TPB   512
#define NTOK  30
#define KP_GATE 1920          // gate stride (rows) in W2 image space
#define NKC   119             // k16 chunks covering 1900
#define R1P   2048            // padded rows, W1 image space (8 rowtiles x 256)
#define R2P   7680            // padded rows, W2 image space (30 rowtiles x 256)
#define A1T   (R1P / 16)      // 128 m16 tiles
#define A2T   (R2P / 16)      // 480 m16 tiles
#define P1KS  18
#define NU1   (8 * P1KS)      // 144
#define NU2   296
#define HB    (Hdim * Bsz)    // 121600
#define SLOT4 1280            // uint4 per pipeline slot (A hi 512 + A lo 512 + B 256)
#define STAGES 4
#define SMEM_BYTES (STAGES * SLOT4 * 16)   // 81920

typedef unsigned int u32;
typedef unsigned short u16;

// ---------------- scratch (__device__ globals; no allocations) ----------------
static __device__ float g_mxT[(size_t)Lseq * HB];
static __device__ float g_hsT[(size_t)Lseq * HB];
static __device__ float g_cT[HB];
static __device__ float g_m1part[P1KS][R1P * Bsz];            // P1 k-split partials [row][b]
static __device__ float g_gpart[10][R2P * Bsz];               // P2 k-split partials [row][b]
static __device__ float g_mxtok[NTOK][Hdim];
static __device__ float g_gxtok[NTOK][Grows];
// fragment-packed operand images (u16 bf16), layout [tile][kc][lane][8 u16]
static __device__ __align__(16) u16 g_w1hi[(size_t)A1T * NKC * 256];
static __device__ __align__(16) u16 g_w1lo[(size_t)A1T * NKC * 256];
static __device__ __align__(16) u16 g_w2hi[(size_t)A2T * NKC * 256];
static __device__ __align__(16) u16 g_w2lo[(size_t)A2T * NKC * 256];
static __device__ __align__(16) u16 g_hpk[8 * NKC * 256];     // h packed (hi+lo interleaved)
static __device__ __align__(16) u16 g_xpk[8 * NKC * 256];     // x2 packed
static __device__ volatile unsigned g_arrive;
static __device__ unsigned g_cnt;
static __device__ volatile unsigned g_gen;

// ---------------- helpers ----------------
__device__ __forceinline__ void bsplit(float v, u16& hi, u16& lo) {
    __nv_bfloat16 h = __float2bfloat16(v);
    hi = *reinterpret_cast<u16*>(&h);
    __nv_bfloat16 l = __float2bfloat16(v - __bfloat162float(h));
    lo = *reinterpret_cast<u16*>(&l);
}
__device__ __forceinline__ void mma_bf16(float d[4], const u32 a0, const u32 a1, const u32 a2, const u32 a3,
                                         const u32 b0, const u32 b1) {
    asm volatile(
        "mma.sync.aligned.m16n8k16.row.col.f32.bf16.bf16.f32 "
        "{%0,%1,%2,%3}, {%4,%5,%6,%7}, {%8,%9}, {%0,%1,%2,%3};"
        : "+f"(d[0]), "+f"(d[1]), "+f"(d[2]), "+f"(d[3])
        : "r"(a0), "r"(a1), "r"(a2), "r"(a3), "r"(b0), "r"(b1));
}
// packed u16 index for B-style images: element (b, k), hi part (+4 for lo)
__device__ __forceinline__ int bpk_idx(int b, int k) {
    return ((((b >> 3) * NKC + (k >> 4)) * 32 + 4 * (b & 7) + ((k & 7) >> 1)) << 3)
           + (((k >> 3) & 1) << 1) + (k & 1);
}
__device__ __forceinline__ void cp16(u32 dsm, const void* src) {
    asm volatile("cp.async.cg.shared.global [%0], [%1], 16;" :: "r"(dsm), "l"(src) : "memory");
}
#define CP_COMMIT() asm volatile("cp.async.commit_group;" ::: "memory")
#define CP_WAIT2()  asm volatile("cp.async.wait_group 2;" ::: "memory")

// ---------------- barriers ----------------
__device__ __forceinline__ void gbarf(unsigned& ep) {
    __syncthreads();
    ep += 1;
    if (threadIdx.x == 0) {
        unsigned tgt = ep * (unsigned)gridDim.x;
        __threadfence();
        atomicAdd((unsigned*)&g_arrive, 1u);
        while ((int)(g_arrive - tgt) < 0) __nanosleep(32);
        __threadfence();
    }
    __syncthreads();
}
__device__ __forceinline__ void gbar_final() {
    __syncthreads();
    if (threadIdx.x == 0) {
        unsigned gen = g_gen;
        __threadfence();
        if (atomicAdd(&g_cnt, 1u) == gridDim.x - 1) {
            g_cnt = 0;
            g_arrive = 0;
            __threadfence();
            g_gen = gen + 1;
        } else {
            while (g_gen == gen) __nanosleep(32);
        }
        __threadfence();
    }
    __syncthreads();
}

// ---------------- block unit: 256 rows x 64 b over k16 chunks [kb0,kb1) ----------------
// 4-stage cp.async ring pipeline: A(hi,lo)+B fragments staged per chunk; MMA reads smem only.
__device__ __forceinline__ void tc_unit(const u16* __restrict__ Whi, const u16* __restrict__ Wlo,
                                        const u16* __restrict__ Bpk,
                                        uint4* __restrict__ slots, u32 slots32,
                                        float* __restrict__ dst,
                                        int rowbase, int kb0, int kb1, int tid, int wid)
{
    const int nch = kb1 - kb0;
    const int mt0 = rowbase >> 4;
    const uint4* Ahg = (const uint4*)Whi;
    const uint4* Alg = (const uint4*)Wlo;
    const uint4* Bpg = (const uint4*)Bpk;
    const int lane = tid & 31;
    const int g = lane >> 2, t4 = lane & 3;

    __syncthreads();   // previous unit's consumers done before slot reuse

    auto stage_chunk = [&](int kc, int slot) {
        u32 dbase = slots32 + (u32)slot * (SLOT4 * 16);
#pragma unroll
        for (int it = 0; it < 3; it++) {
            int idx = it * TPB + tid;
            if (idx < SLOT4) {
                const uint4* src;
                if (idx < 512)
                    src = Ahg + ((size_t)(mt0 + (idx >> 5)) * NKC + kc) * 32 + (idx & 31);
                else if (idx < 1024) {
                    int r = idx - 512;
                    src = Alg + ((size_t)(mt0 + (r >> 5)) * NKC + kc) * 32 + (r & 31);
                } else {
                    int r = idx - 1024;
                    src = Bpg + ((size_t)(r >> 5) * NKC + kc) * 32 + (r & 31);
                }
                cp16(dbase + (u32)idx * 16, src);
            }
        }
    };

    // prologue: stage up to 3 chunks (always 3 commits)
#pragma unroll
    for (int s = 0; s < STAGES - 1; s++) {
        if (s < nch) stage_chunk(kb0 + s, s);
        CP_COMMIT();
    }

    float d[8][4];
#pragma unroll
    for (int n = 0; n < 8; n++)
#pragma unroll
        for (int q = 0; q < 4; q++) d[n][q] = 0.f;

    for (int c = 0; c < nch; c++) {
        CP_WAIT2();          // group for chunk c complete (c+1,c+2 may be pending)
        __syncthreads();
        const uint4* sl = slots + (size_t)(c & (STAGES - 1)) * SLOT4;
        uint4 ah = sl[wid * 32 + lane];
        uint4 al = sl[512 + wid * 32 + lane];
#pragma unroll
        for (int n = 0; n < 8; n++) {
            uint4 bp = sl[1024 + n * 32 + lane];
            mma_bf16(d[n], ah.x, ah.y, ah.z, ah.w, bp.x, bp.y); // hi*hi
            mma_bf16(d[n], ah.x, ah.y, ah.z, ah.w, bp.z, bp.w); // hi*lo
            mma_bf16(d[n], al.x, al.y, al.z, al.w, bp.x, bp.y); // lo*hi
        }
        __syncthreads();     // consumers done before restaging this ring slot window
        if (c + STAGES - 1 < nch) stage_chunk(kb0 + c + STAGES - 1, (c + STAGES - 1) & (STAGES - 1));
        CP_COMMIT();
    }

    // ---- writeback ----
    int r = (mt0 + wid) * 16 + g;
#pragma unroll
    for (int n = 0; n < 8; n++) {
        *(float2*)(dst + (size_t)r * 64 + n * 8 + 2 * t4)       = make_float2(d[n][0], d[n][1]);
        *(float2*)(dst + (size_t)(r + 8) * 64 + n * 8 + 2 * t4) = make_float2(d[n][2], d[n][3]);
    }
}

// ---------------- persistent kernel ----------------
__global__ void __launch_bounds__(TPB, 1) uni_kernel(
    const int*   __restrict__ xb,
    const float* __restrict__ h0,    const float* __restrict__ c0,
    const float* __restrict__ etab,
    const float* __restrict__ w_mx,  const float* __restrict__ w_mh,
    const float* __restrict__ w_ih,  const float* __restrict__ w_hm,
    const float* __restrict__ bias,
    const float* __restrict__ w_lin, const float* __restrict__ b_lin,
    float* __restrict__ out)
{
    extern __shared__ __align__(16) char dsm[];
    uint4* slots = (uint4*)dsm;
    u32 slots32 = (u32)__cvta_generic_to_shared(dsm);
    float* s_proj = (float*)dsm;       // overlay for final projection
    __shared__ int s_tok[Bsz];

    const int tid = threadIdx.x;
    const int wid = tid >> 5;          // 0..15
    const int gid = blockIdx.x * TPB + tid;
    const int gstride = gridDim.x * TPB;
    unsigned ep = 0;

    // ================= pre phase A =================
    for (int i = gid; i < NTOK * Hdim; i += gstride) {
        int v = i / Hdim, j = i - v * Hdim;
        float a = 0.f;
        if (v != 0)
#pragma unroll
            for (int e = 0; e < Edim; e++)
                a = fmaf(etab[(size_t)v * Edim + e], w_mx[(size_t)j * Edim + e], a);
        g_mxtok[v][j] = a;
    }
    for (int i = gid; i < NTOK * Grows; i += gstride) {
        int v = i / Grows, r = i - v * Grows;
        float a = bias[r];
        if (v != 0)
#pragma unroll
            for (int e = 0; e < Edim; e++)
                a = fmaf(etab[(size_t)v * Edim + e], w_ih[(size_t)r * Edim + e], a);
        g_gxtok[v][r] = a;
    }
    for (int i = gid; i < HB; i += gstride) {
        int j = i >> 6, b = i & 63;
        g_cT[i] = c0[(size_t)b * Hdim + j];
    }
    for (int i = gid; i < 8 * NKC * 256; i += gstride) { g_hpk[i] = 0; g_xpk[i] = 0; }
    gbarf(ep);
    for (int i = gid; i < HB; i += gstride) {
        int j = i >> 6, b = i & 63;
        u16 hi, lo; bsplit(h0[(size_t)b * Hdim + j], hi, lo);
        int p = bpk_idx(b, j);
        g_hpk[p] = hi; g_hpk[p + 4] = lo;
    }
    for (int i = gid; i < R2P * Bsz; i += gstride) g_gpart[9][i] = 0.f;
    // W1 fragment-packed image (w_mh)
    for (size_t i = gid; i < (size_t)A1T * NKC * 256; i += gstride) {
        int mt = (int)(i / (NKC * 256));
        int rem = (int)(i - (size_t)mt * (NKC * 256));
        int kc = rem >> 8, r2 = rem & 255;
        int lane = r2 >> 3, e = r2 & 7;
        int g = lane >> 2, t4 = lane & 3;
        int q = e >> 1, bit = e & 1;
        int row = mt * 16 + g + ((q & 1) ? 8 : 0);
        int col = kc * 16 + 2 * t4 + ((q & 2) ? 8 : 0) + bit;
        float v = (row < Hdim && col < Hdim) ? w_mh[(size_t)row * Hdim + col] : 0.f;
        u16 hi, lo; bsplit(v, hi, lo);
        g_w1hi[i] = hi; g_w1lo[i] = lo;
    }
    // W2 fragment-packed image (w_hm); image row = gate*1920 + hj
    for (size_t i = gid; i < (size_t)A2T * NKC * 256; i += gstride) {
        int mt = (int)(i / (NKC * 256));
        int rem = (int)(i - (size_t)mt * (NKC * 256));
        int kc = rem >> 8, r2 = rem & 255;
        int lane = r2 >> 3, e = r2 & 7;
        int g = lane >> 2, t4 = lane & 3;
        int q = e >> 1, bit = e & 1;
        int row = mt * 16 + g + ((q & 1) ? 8 : 0);
        int col = kc * 16 + 2 * t4 + ((q & 2) ? 8 : 0) + bit;
        int gate = row / KP_GATE, hj = row - gate * KP_GATE;
        float v = 0.f;
        if (hj < Hdim && col < Hdim)
            v = w_hm[((size_t)gate * Hdim + hj) * Hdim + col];
        u16 hi, lo; bsplit(v, hi, lo);
        g_w2hi[i] = hi; g_w2lo[i] = lo;
    }
    gbarf(ep);

    // ================= pre phase B: mxT =================
    for (int unit = blockIdx.x; unit < Lseq; unit += gridDim.x) {
        __syncthreads();
        if (tid < Bsz) s_tok[tid] = xb[(size_t)tid * Lseq + unit];
        __syncthreads();
        float* dst = g_mxT + (size_t)unit * HB;
        for (int i = tid; i < HB; i += TPB) {
            int j = i >> 6, b = i & 63;
            dst[i] = g_mxtok[s_tok[b]][j];
        }
    }
    gbarf(ep);

    // ================= recurrent loop =================
    for (int t = 0; t < Lseq; t++) {
        // ---- P1: mdot partials = w_mh @ h (144 units: 8 rowtiles x 18 ksplits) ----
        for (int u = blockIdx.x; u < NU1; u += gridDim.x) {
            int rt = u / P1KS, ks = u - rt * P1KS;
            int kb0 = (ks * NKC) / P1KS, kb1 = ((ks + 1) * NKC) / P1KS;
            tc_unit(g_w1hi, g_w1lo, g_hpk, slots, slots32, g_m1part[ks],
                    rt * 256, kb0, kb1, tid, wid);
        }
        gbarf(ep);

        // ---- P1.5: reduce partials, x2 = mdot*mx, scatter into packed x image ----
        {
            const float4* mx4 = (const float4*)(g_mxT + (size_t)t * HB);
            for (int i = gid; i < HB / 4; i += gstride) {
                float4 s = ((const float4*)g_m1part[0])[i];
#pragma unroll
                for (int ks = 1; ks < P1KS; ks++) {
                    float4 p = ((const float4*)g_m1part[ks])[i];
                    s.x += p.x; s.y += p.y; s.z += p.z; s.w += p.w;
                }
                float4 m = mx4[i];
                s.x *= m.x; s.y *= m.y; s.z *= m.z; s.w *= m.w;
                int j = i >> 4, b0 = (i & 15) * 4;
                const float* ps = (const float*)&s;
#pragma unroll
                for (int q = 0; q < 4; q++) {
                    u16 hi, lo; bsplit(ps[q], hi, lo);
                    int p = bpk_idx(b0 + q, j);
                    g_xpk[p] = hi; g_xpk[p + 4] = lo;
                }
            }
        }
        gbarf(ep);

        // ---- P2: gate partials = w_hm @ x2 (296 ragged units over 30 rowtiles) ----
        for (int u = blockIdx.x; u < NU2; u += gridDim.x) {
            int ks = u / 30, rt = u - ks * 30;
            int nks = (rt < 26) ? 10 : 9;
            int kb0 = (ks * NKC) / nks, kb1 = ((ks + 1) * NKC) / nks;
            tc_unit(g_w2hi, g_w2lo, g_xpk, slots, slots32, g_gpart[ks],
                    rt * 256, kb0, kb1, tid, wid);
        }
        gbarf(ep);

        // ---- P3: gates + c/h update + hs + packed h scatter ----
        {
            __syncthreads();
            if (tid < Bsz) s_tok[tid] = xb[(size_t)tid * Lseq + t];
            __syncthreads();
            float* hs = g_hsT + (size_t)t * HB;
            for (int i = gid; i < HB / 4; i += gstride) {
                int hj = i >> 4, b0 = (i & 15) * 4;
                float4 gv[4];
#pragma unroll
                for (int gg = 0; gg < 4; gg++) {
                    int r = gg * KP_GATE + hj;
                    float4 a;
                    a.x = g_gxtok[s_tok[b0]][gg * Hdim + hj];
                    a.y = g_gxtok[s_tok[b0 + 1]][gg * Hdim + hj];
                    a.z = g_gxtok[s_tok[b0 + 2]][gg * Hdim + hj];
                    a.w = g_gxtok[s_tok[b0 + 3]][gg * Hdim + hj];
#pragma unroll
                    for (int ks = 0; ks < 10; ks++) {
                        float4 p = *(const float4*)(g_gpart[ks] + (size_t)r * 64 + b0);
                        a.x += p.x; a.y += p.y; a.z += p.z; a.w += p.w;
                    }
                    gv[gg] = a;
                }
                float4 c4 = ((const float4*)g_cT)[i];
                float4 h4;
                const float* pi = (const float*)&gv[0];
                const float* pf = (const float*)&gv[1];
                const float* pg = (const float*)&gv[2];
                const float* po = (const float*)&gv[3];
                float* pc = (float*)&c4;
                float* ph = (float*)&h4;
#pragma unroll
                for (int q = 0; q < 4; q++) {
                    float si = __fdividef(1.f, 1.f + __expf(-pi[q]));
                    float sf = __fdividef(1.f, 1.f + __expf(-pf[q]));
                    float so = __fdividef(1.f, 1.f + __expf(-po[q]));
                    float c = sf * pc[q] + si * tanhf(pg[q]);
                    pc[q] = c;
                    float h = so * tanhf(c);
                    ph[q] = h;
                    u16 hi, lo; bsplit(h, hi, lo);
                    int p = bpk_idx(b0 + q, hj);
                    g_hpk[p] = hi; g_hpk[p + 4] = lo;
                }
                ((float4*)g_cT)[i] = c4;
                ((float4*)hs)[i] = h4;
            }
        }
        gbarf(ep);
    }
    gbar_final();

    // ================= final projection =================
    for (int unit = blockIdx.x; unit < Lseq; unit += gridDim.x) {
        const float* X = g_hsT + (size_t)unit * HB;
        float acc[4];
#pragma unroll
        for (int q = 0; q < 4; q++) acc[q] = 0.f;
        int b = tid & 63, ng = tid >> 6;   // ng 0..7
        for (int kt = 0; kt < 60; kt++) {
            int k0 = kt * 32;
            __syncthreads();
#pragma unroll
            for (int u = 0; u < 4; u++) {
                int idx = u * TPB + tid;
                int k = k0 + (idx >> 6);
                s_proj[idx] = (k < Hdim) ? X[(size_t)k0 * 64 + idx] : 0.f;
            }
            __syncthreads();
            int klim = Hdim - k0; if (klim > 32) klim = 32;
            for (int kk = 0; kk < klim; kk++) {
                float xv = s_proj[kk * 64 + b];
#pragma unroll
                for (int q = 0; q < 4; q++) {
                    int n = ng + q * 8;
                    if (n < NOUT) acc[q] = fmaf(xv, w_lin[(size_t)n * Hdim + k0 + kk], acc[q]);
                }
            }
        }
#pragma unroll
        for (int q = 0; q < 4; q++) {
            int n = ng + q * 8;
            if (n < NOUT)
                out[((size_t)b * Lseq + unit) * NOUT + n] = acc[q] + b_lin[n];
        }
    }
}

// ---------------- launcher: ONE graph node ----------------
extern "C" void kernel_launch(void* const* d_in, const int* in_sizes, int n_in,
                              void* d_out, int out_size)
{
    (void)in_sizes; (void)n_in; (void)out_size;
    const int*   xb    = (const int*)  d_in[0];
    // d_in[1] = xb_lens (unused by the reference math)
    const float* h0    = (const float*)d_in[2];
    const float* c0    = (const float*)d_in[3];
    const float* etab  = (const float*)d_in[4];
    const float* w_mx  = (const float*)d_in[5];
    const float* w_mh  = (const float*)d_in[6];
    const float* w_ih  = (const float*)d_in[7];
    const float* w_hm  = (const float*)d_in[8];
    const float* bias  = (const float*)d_in[9];
    const float* w_lin = (const float*)d_in[10];
    const float* b_lin = (const float*)d_in[11];
    float* out = (float*)d_out;

    static int smem_set = 0;
    if (!smem_set) {
        cudaFuncSetAttribute(uni_kernel, cudaFuncAttributeMaxDynamicSharedMemorySize, SMEM_BYTES);
        smem_set = 1;
    }

    int sms = 0;
    if (cudaDeviceGetAttribute(&sms, cudaDevAttrMultiProcessorCount, 0) != cudaSuccess || sms <= 0)
        sms = 148;

    uni_kernel<<<sms, TPB, SMEM_BYTES>>>(xb, h0, c0, etab, w_mx, w_mh, w_ih, w_hm,
                                         bias, w_lin, b_lin, out);
}

// round 14
// speedup vs baseline: 1.1281x; 1.1281x over previous
#include <cuda_runtime.h>
#include <cuda_bf16.h>
#include <math.h>
#include <stdint.h>

#define Bsz   64
#define Lseq  512
#define Edim  10
#define Hdim  1900
#define Grows 7600
#define NOUT  25
#define TPB   512
#define NTOK  30
#define KP_GATE 1920          // gate stride (rows) in W2 image space
#define NKC   119             // k16 chunks covering 1900
#define R1P   2048            // padded rows, W1 image space (8 rowtiles x 256)
#define R2P   7680            // padded rows, W2 image space (30 rowtiles x 256)
#define A1T   (R1P / 16)      // 128 m16 tiles
#define A2T   (R2P / 16)      // 480 m16 tiles
#define P1KS  18
#define NU1   (8 * P1KS)      // 144
#define NU2   296
#define HB    (Hdim * Bsz)    // 121600
#define NCMAX 14              // max k16 chunks per unit
#define SMEM_BYTES (NCMAX * 256 * 16)   // 57344 B: staged B fragments

typedef unsigned int u32;
typedef unsigned short u16;

// ---------------- scratch (__device__ globals; no allocations) ----------------
static __device__ float g_mxT[(size_t)Lseq * HB];
static __device__ float g_hsT[(size_t)Lseq * HB];
static __device__ float g_cT[HB];
static __device__ float g_m1part[P1KS][R1P * Bsz];            // P1 k-split partials [row][b]
static __device__ float g_gpart[10][R2P * Bsz];               // P2 k-split partials [row][b]
static __device__ float g_mxtok[NTOK][Hdim];
static __device__ float g_gxtok[NTOK][Grows];
// fragment-packed operand images (u16 bf16), layout [tile][kc][lane][8 u16]
static __device__ __align__(16) u16 g_w1hi[(size_t)A1T * NKC * 256];
static __device__ __align__(16) u16 g_w1lo[(size_t)A1T * NKC * 256];
static __device__ __align__(16) u16 g_w2hi[(size_t)A2T * NKC * 256];
static __device__ __align__(16) u16 g_w2lo[(size_t)A2T * NKC * 256];
static __device__ __align__(16) u16 g_hpk[8 * NKC * 256];     // h packed (hi+lo interleaved)
static __device__ __align__(16) u16 g_xpk[8 * NKC * 256];     // x2 packed
static __device__ volatile unsigned g_arrive;
static __device__ unsigned g_cnt;
static __device__ volatile unsigned g_gen;

// ---------------- helpers ----------------
__device__ __forceinline__ void bsplit(float v, u16& hi, u16& lo) {
    __nv_bfloat16 h = __float2bfloat16(v);
    hi = *reinterpret_cast<u16*>(&h);
    __nv_bfloat16 l = __float2bfloat16(v - __bfloat162float(h));
    lo = *reinterpret_cast<u16*>(&l);
}
__device__ __forceinline__ void mma_bf16(float d[4], const u32 a0, const u32 a1, const u32 a2, const u32 a3,
                                         const u32 b0, const u32 b1) {
    asm volatile(
        "mma.sync.aligned.m16n8k16.row.col.f32.bf16.bf16.f32 "
        "{%0,%1,%2,%3}, {%4,%5,%6,%7}, {%8,%9}, {%0,%1,%2,%3};"
        : "+f"(d[0]), "+f"(d[1]), "+f"(d[2]), "+f"(d[3])
        : "r"(a0), "r"(a1), "r"(a2), "r"(a3), "r"(b0), "r"(b1));
}
// packed u16 index for B-style images: element (b, k), hi part (+4 for lo)
__device__ __forceinline__ int bpk_idx(int b, int k) {
    return ((((b >> 3) * NKC + (k >> 4)) * 32 + 4 * (b & 7) + ((k & 7) >> 1)) << 3)
           + (((k >> 3) & 1) << 1) + (k & 1);
}

// ---------------- barriers ----------------
__device__ __forceinline__ void gbarf(unsigned& ep) {
    __syncthreads();
    ep += 1;
    if (threadIdx.x == 0) {
        unsigned tgt = ep * (unsigned)gridDim.x;
        __threadfence();
        atomicAdd((unsigned*)&g_arrive, 1u);
        while ((int)(g_arrive - tgt) < 0) __nanosleep(32);
        __threadfence();
    }
    __syncthreads();
}
__device__ __forceinline__ void gbar_final() {
    __syncthreads();
    if (threadIdx.x == 0) {
        unsigned gen = g_gen;
        __threadfence();
        if (atomicAdd(&g_cnt, 1u) == gridDim.x - 1) {
            g_cnt = 0;
            g_arrive = 0;
            __threadfence();
            g_gen = gen + 1;
        } else {
            while (g_gen == gen) __nanosleep(32);
        }
        __threadfence();
    }
    __syncthreads();
}

// ---------------- block unit: 256 rows x 64 b over k16 chunks [kb0,kb1) ----------------
// B k-range staged into smem cooperatively; A register double-buffered from global.
// MMA issued TERM-MAJOR: 8 independent accumulators per term -> dependent distance 8.
__device__ __forceinline__ void tc_unit(const u16* __restrict__ Whi, const u16* __restrict__ Wlo,
                                        const u16* __restrict__ Bpk, uint4* __restrict__ sB4,
                                        float* __restrict__ dst,
                                        int rowbase, int kb0, int kb1, int tid, int wid)
{
    const int nchunks = kb1 - kb0;

    // ---- stage B fragments for this k-range into smem (coalesced uint4) ----
    __syncthreads();    // previous unit's readers done before overwrite
    const uint4* Bp = (const uint4*)Bpk;
    for (int idx = tid; idx < nchunks * 256; idx += TPB) {
        int c = idx >> 8, r = idx & 255;
        int n = r >> 5, ln = r & 31;
        sB4[idx] = Bp[((size_t)n * NKC + kb0 + c) * 32 + ln];
    }
    __syncthreads();

    // ---- per-warp MMA: warp wid handles m16 tile rowbase/16 + wid ----
    const int lane = tid & 31;
    const int g = lane >> 2, t4 = lane & 3;
    const int mt = (rowbase >> 4) + wid;
    const uint4* Ah = (const uint4*)Whi;
    const uint4* Al = (const uint4*)Wlo;

    float d[8][4];
#pragma unroll
    for (int n = 0; n < 8; n++)
#pragma unroll
        for (int q = 0; q < 4; q++) d[n][q] = 0.f;

    const size_t abase = ((size_t)mt * NKC + kb0) * 32 + lane;
    uint4 ahc = Ah[abase];
    uint4 alc = Al[abase];

    for (int c = 0; c < nchunks; c++) {
        uint4 ahn, aln;
        if (c + 1 < nchunks) {              // prefetch next A chunk before MMAs
            ahn = Ah[abase + (size_t)(c + 1) * 32];
            aln = Al[abase + (size_t)(c + 1) * 32];
        }
        const uint4* bs = sB4 + c * 256 + lane;
        uint4 bp[8];
#pragma unroll
        for (int n = 0; n < 8; n++) bp[n] = bs[n * 32];
        // term-major: all 8 accumulators per term -> dependency distance 8
#pragma unroll
        for (int n = 0; n < 8; n++)
            mma_bf16(d[n], ahc.x, ahc.y, ahc.z, ahc.w, bp[n].x, bp[n].y); // hi*hi
#pragma unroll
        for (int n = 0; n < 8; n++)
            mma_bf16(d[n], ahc.x, ahc.y, ahc.z, ahc.w, bp[n].z, bp[n].w); // hi*lo
#pragma unroll
        for (int n = 0; n < 8; n++)
            mma_bf16(d[n], alc.x, alc.y, alc.z, alc.w, bp[n].x, bp[n].y); // lo*hi
        ahc = ahn; alc = aln;
    }

    // ---- writeback ----
    int r = mt * 16 + g;
#pragma unroll
    for (int n = 0; n < 8; n++) {
        *(float2*)(dst + (size_t)r * 64 + n * 8 + 2 * t4)       = make_float2(d[n][0], d[n][1]);
        *(float2*)(dst + (size_t)(r + 8) * 64 + n * 8 + 2 * t4) = make_float2(d[n][2], d[n][3]);
    }
}

// ---------------- persistent kernel ----------------
__global__ void __launch_bounds__(TPB, 1) uni_kernel(
    const int*   __restrict__ xb,
    const float* __restrict__ h0,    const float* __restrict__ c0,
    const float* __restrict__ etab,
    const float* __restrict__ w_mx,  const float* __restrict__ w_mh,
    const float* __restrict__ w_ih,  const float* __restrict__ w_hm,
    const float* __restrict__ bias,
    const float* __restrict__ w_lin, const float* __restrict__ b_lin,
    float* __restrict__ out)
{
    extern __shared__ __align__(16) char dsm[];
    uint4* sB4 = (uint4*)dsm;          // B fragment staging (57 KB)
    float* s_proj = (float*)dsm;       // overlay for final projection
    __shared__ int s_tok[Bsz];

    const int tid = threadIdx.x;
    const int wid = tid >> 5;          // 0..15
    const int gid = blockIdx.x * TPB + tid;
    const int gstride = gridDim.x * TPB;
    unsigned ep = 0;

    // ================= pre phase A =================
    for (int i = gid; i < NTOK * Hdim; i += gstride) {
        int v = i / Hdim, j = i - v * Hdim;
        float a = 0.f;
        if (v != 0)
#pragma unroll
            for (int e = 0; e < Edim; e++)
                a = fmaf(etab[(size_t)v * Edim + e], w_mx[(size_t)j * Edim + e], a);
        g_mxtok[v][j] = a;
    }
    for (int i = gid; i < NTOK * Grows; i += gstride) {
        int v = i / Grows, r = i - v * Grows;
        float a = bias[r];
        if (v != 0)
#pragma unroll
            for (int e = 0; e < Edim; e++)
                a = fmaf(etab[(size_t)v * Edim + e], w_ih[(size_t)r * Edim + e], a);
        g_gxtok[v][r] = a;
    }
    for (int i = gid; i < HB; i += gstride) {
        int j = i >> 6, b = i & 63;
        g_cT[i] = c0[(size_t)b * Hdim + j];
    }
    for (int i = gid; i < 8 * NKC * 256; i += gstride) { g_hpk[i] = 0; g_xpk[i] = 0; }
    gbarf(ep);
    for (int i = gid; i < HB; i += gstride) {
        int j = i >> 6, b = i & 63;
        u16 hi, lo; bsplit(h0[(size_t)b * Hdim + j], hi, lo);
        int p = bpk_idx(b, j);
        g_hpk[p] = hi; g_hpk[p + 4] = lo;
    }
    for (int i = gid; i < R2P * Bsz; i += gstride) g_gpart[9][i] = 0.f;
    // W1 fragment-packed image (w_mh)
    for (size_t i = gid; i < (size_t)A1T * NKC * 256; i += gstride) {
        int mt = (int)(i / (NKC * 256));
        int rem = (int)(i - (size_t)mt * (NKC * 256));
        int kc = rem >> 8, r2 = rem & 255;
        int lane = r2 >> 3, e = r2 & 7;
        int g = lane >> 2, t4 = lane & 3;
        int q = e >> 1, bit = e & 1;
        int row = mt * 16 + g + ((q & 1) ? 8 : 0);
        int col = kc * 16 + 2 * t4 + ((q & 2) ? 8 : 0) + bit;
        float v = (row < Hdim && col < Hdim) ? w_mh[(size_t)row * Hdim + col] : 0.f;
        u16 hi, lo; bsplit(v, hi, lo);
        g_w1hi[i] = hi; g_w1lo[i] = lo;
    }
    // W2 fragment-packed image (w_hm); image row = gate*1920 + hj
    for (size_t i = gid; i < (size_t)A2T * NKC * 256; i += gstride) {
        int mt = (int)(i / (NKC * 256));
        int rem = (int)(i - (size_t)mt * (NKC * 256));
        int kc = rem >> 8, r2 = rem & 255;
        int lane = r2 >> 3, e = r2 & 7;
        int g = lane >> 2, t4 = lane & 3;
        int q = e >> 1, bit = e & 1;
        int row = mt * 16 + g + ((q & 1) ? 8 : 0);
        int col = kc * 16 + 2 * t4 + ((q & 2) ? 8 : 0) + bit;
        int gate = row / KP_GATE, hj = row - gate * KP_GATE;
        float v = 0.f;
        if (hj < Hdim && col < Hdim)
            v = w_hm[((size_t)gate * Hdim + hj) * Hdim + col];
        u16 hi, lo; bsplit(v, hi, lo);
        g_w2hi[i] = hi; g_w2lo[i] = lo;
    }
    gbarf(ep);

    // ================= pre phase B: mxT =================
    for (int unit = blockIdx.x; unit < Lseq; unit += gridDim.x) {
        __syncthreads();
        if (tid < Bsz) s_tok[tid] = xb[(size_t)tid * Lseq + unit];
        __syncthreads();
        float* dst = g_mxT + (size_t)unit * HB;
        for (int i = tid; i < HB; i += TPB) {
            int j = i >> 6, b = i & 63;
            dst[i] = g_mxtok[s_tok[b]][j];
        }
    }
    gbarf(ep);

    // ================= recurrent loop =================
    for (int t = 0; t < Lseq; t++) {
        // ---- P1: mdot partials = w_mh @ h (144 units: 8 rowtiles x 18 ksplits) ----
        for (int u = blockIdx.x; u < NU1; u += gridDim.x) {
            int rt = u / P1KS, ks = u - rt * P1KS;
            int kb0 = (ks * NKC) / P1KS, kb1 = ((ks + 1) * NKC) / P1KS;
            tc_unit(g_w1hi, g_w1lo, g_hpk, sB4, g_m1part[ks],
                    rt * 256, kb0, kb1, tid, wid);
        }
        gbarf(ep);

        // ---- P1.5: reduce partials, x2 = mdot*mx, scatter into packed x image ----
        {
            const float4* mx4 = (const float4*)(g_mxT + (size_t)t * HB);
            for (int i = gid; i < HB / 4; i += gstride) {
                float4 s = ((const float4*)g_m1part[0])[i];
#pragma unroll
                for (int ks = 1; ks < P1KS; ks++) {
                    float4 p = ((const float4*)g_m1part[ks])[i];
                    s.x += p.x; s.y += p.y; s.z += p.z; s.w += p.w;
                }
                float4 m = mx4[i];
                s.x *= m.x; s.y *= m.y; s.z *= m.z; s.w *= m.w;
                int j = i >> 4, b0 = (i & 15) * 4;
                const float* ps = (const float*)&s;
#pragma unroll
                for (int q = 0; q < 4; q++) {
                    u16 hi, lo; bsplit(ps[q], hi, lo);
                    int p = bpk_idx(b0 + q, j);
                    g_xpk[p] = hi; g_xpk[p + 4] = lo;
                }
            }
        }
        gbarf(ep);

        // ---- P2: gate partials = w_hm @ x2 (296 ragged units over 30 rowtiles) ----
        for (int u = blockIdx.x; u < NU2; u += gridDim.x) {
            int ks = u / 30, rt = u - ks * 30;
            int nks = (rt < 26) ? 10 : 9;
            int kb0 = (ks * NKC) / nks, kb1 = ((ks + 1) * NKC) / nks;
            tc_unit(g_w2hi, g_w2lo, g_xpk, sB4, g_gpart[ks],
                    rt * 256, kb0, kb1, tid, wid);
        }
        gbarf(ep);

        // ---- P3: gates + c/h update + hs + packed h scatter ----
        {
            __syncthreads();
            if (tid < Bsz) s_tok[tid] = xb[(size_t)tid * Lseq + t];
            __syncthreads();
            float* hs = g_hsT + (size_t)t * HB;
            for (int i = gid; i < HB / 4; i += gstride) {
                int hj = i >> 4, b0 = (i & 15) * 4;
                float4 gv[4];
#pragma unroll
                for (int gg = 0; gg < 4; gg++) {
                    int r = gg * KP_GATE + hj;
                    float4 a;
                    a.x = g_gxtok[s_tok[b0]][gg * Hdim + hj];
                    a.y = g_gxtok[s_tok[b0 + 1]][gg * Hdim + hj];
                    a.z = g_gxtok[s_tok[b0 + 2]][gg * Hdim + hj];
                    a.w = g_gxtok[s_tok[b0 + 3]][gg * Hdim + hj];
#pragma unroll
                    for (int ks = 0; ks < 10; ks++) {
                        float4 p = *(const float4*)(g_gpart[ks] + (size_t)r * 64 + b0);
                        a.x += p.x; a.y += p.y; a.z += p.z; a.w += p.w;
                    }
                    gv[gg] = a;
                }
                float4 c4 = ((const float4*)g_cT)[i];
                float4 h4;
                const float* pi = (const float*)&gv[0];
                const float* pf = (const float*)&gv[1];
                const float* pg = (const float*)&gv[2];
                const float* po = (const float*)&gv[3];
                float* pc = (float*)&c4;
                float* ph = (float*)&h4;
#pragma unroll
                for (int q = 0; q < 4; q++) {
                    float si = __fdividef(1.f, 1.f + __expf(-pi[q]));
                    float sf = __fdividef(1.f, 1.f + __expf(-pf[q]));
                    float so = __fdividef(1.f, 1.f + __expf(-po[q]));
                    float c = sf * pc[q] + si * tanhf(pg[q]);
                    pc[q] = c;
                    float h = so * tanhf(c);
                    ph[q] = h;
                    u16 hi, lo; bsplit(h, hi, lo);
                    int p = bpk_idx(b0 + q, hj);
                    g_hpk[p] = hi; g_hpk[p + 4] = lo;
                }
                ((float4*)g_cT)[i] = c4;
                ((float4*)hs)[i] = h4;
            }
        }
        gbarf(ep);
    }
    gbar_final();

    // ================= final projection =================
    for (int unit = blockIdx.x; unit < Lseq; unit += gridDim.x) {
        const float* X = g_hsT + (size_t)unit * HB;
        float acc[4];
#pragma unroll
        for (int q = 0; q < 4; q++) acc[q] = 0.f;
        int b = tid & 63, ng = tid >> 6;   // ng 0..7
        for (int kt = 0; kt < 60; kt++) {
            int k0 = kt * 32;
            __syncthreads();
#pragma unroll
            for (int u = 0; u < 4; u++) {
                int idx = u * TPB + tid;
                int k = k0 + (idx >> 6);
                s_proj[idx] = (k < Hdim) ? X[(size_t)k0 * 64 + idx] : 0.f;
            }
            __syncthreads();
            int klim = Hdim - k0; if (klim > 32) klim = 32;
            for (int kk = 0; kk < klim; kk++) {
                float xv = s_proj[kk * 64 + b];
#pragma unroll
                for (int q = 0; q < 4; q++) {
                    int n = ng + q * 8;
                    if (n < NOUT) acc[q] = fmaf(xv, w_lin[(size_t)n * Hdim + k0 + kk], acc[q]);
                }
            }
        }
#pragma unroll
        for (int q = 0; q < 4; q++) {
            int n = ng + q * 8;
            if (n < NOUT)
                out[((size_t)b * Lseq + unit) * NOUT + n] = acc[q] + b_lin[n];
        }
    }
}

// ---------------- launcher: ONE graph node ----------------
extern "C" void kernel_launch(void* const* d_in, const int* in_sizes, int n_in,
                              void* d_out, int out_size)
{
    (void)in_sizes; (void)n_in; (void)out_size;
    const int*   xb    = (const int*)  d_in[0];
    // d_in[1] = xb_lens (unused by the reference math)
    const float* h0    = (const float*)d_in[2];
    const float* c0    = (const float*)d_in[3];
    const float* etab  = (const float*)d_in[4];
    const float* w_mx  = (const float*)d_in[5];
    const float* w_mh  = (const float*)d_in[6];
    const float* w_ih  = (const float*)d_in[7];
    const float* w_hm  = (const float*)d_in[8];
    const float* bias  = (const float*)d_in[9];
    const float* w_lin = (const float*)d_in[10];
    const float* b_lin = (const float*)d_in[11];
    float* out = (float*)d_out;

    static int smem_set = 0;
    if (!smem_set) {
        cudaFuncSetAttribute(uni_kernel, cudaFuncAttributeMaxDynamicSharedMemorySize, SMEM_BYTES);
        smem_set = 1;
    }

    int sms = 0;
    if (cudaDeviceGetAttribute(&sms, cudaDevAttrMultiProcessorCount, 0) != cudaSuccess || sms <= 0)
        sms = 148;

    uni_kernel<<<sms, TPB, SMEM_BYTES>>>(xb, h0, c0, etab, w_mx, w_mh, w_ih, w_hm,
                                         bias, w_lin, b_lin, out);
}

// round 15
// speedup vs baseline: 1.4477x; 1.2833x over previous
#include <cuda_runtime.h>
#include <cuda_fp16.h>
#include <math.h>
#include <stdint.h>

#define Bsz   64
#define Lseq  512
#define Edim  10
#define Hdim  1900
#define Grows 7600
#define NOUT  25
#define TPB   512
#define NTOK  30
#define KP_GATE 1920          // gate stride (rows) in W2 image space
#define NKC   119             // k16 chunks covering 1900
#define R1P   2048            // padded rows, W1 image space (8 rowtiles x 256)
#define R2P   7680            // padded rows, W2 image space (30 rowtiles x 256)
#define A1T   (R1P / 16)      // 128 m16 tiles
#define A2T   (R2P / 16)      // 480 m16 tiles
#define P1KS  18
#define NU1   (8 * P1KS)      // 144
#define NU2   296
#define HB    (Hdim * Bsz)    // 121600
#define NCMAX 14              // max k16 chunks per unit
#define SMEM_BYTES (NCMAX * 256 * 16)   // 57344 B: staged B fragments

typedef unsigned int u32;
typedef unsigned short u16;

// ---------------- scratch (__device__ globals; no allocations) ----------------
static __device__ float g_mxT[(size_t)Lseq * HB];
static __device__ float g_hsT[(size_t)Lseq * HB];
static __device__ float g_cT[HB];
static __device__ float g_m1part[P1KS][R1P * Bsz];            // P1 k-split partials [row][b]
static __device__ float g_gpart[10][R2P * Bsz];               // P2 k-split partials [row][b]
static __device__ float g_mxtok[NTOK][Hdim];
static __device__ float g_gxtok[NTOK][Grows];
// fragment-packed operand images (u16 = fp16 bits), layout [tile][kc][lane][8 u16]
static __device__ __align__(16) u16 g_w1h[(size_t)A1T * NKC * 256];   // w_mh fp16
static __device__ __align__(16) u16 g_w2h[(size_t)A2T * NKC * 256];   // w_hm fp16
static __device__ __align__(16) u16 g_hpk[8 * NKC * 256];     // h packed (hi+lo fp16)
static __device__ __align__(16) u16 g_xpk[8 * NKC * 256];     // x2 packed (hi+lo fp16)
static __device__ volatile unsigned g_arrive;
static __device__ unsigned g_cnt;
static __device__ volatile unsigned g_gen;

// ---------------- helpers ----------------
__device__ __forceinline__ u16 f2h(float v) {
    __half h = __float2half_rn(v);
    return *reinterpret_cast<u16*>(&h);
}
__device__ __forceinline__ void hsplit(float v, u16& hi, u16& lo) {
    __half h = __float2half_rn(v);
    hi = *reinterpret_cast<u16*>(&h);
    __half l = __float2half_rn(v - __half2float(h));
    lo = *reinterpret_cast<u16*>(&l);
}
__device__ __forceinline__ void mma_f16(float d[4], const u32 a0, const u32 a1, const u32 a2, const u32 a3,
                                        const u32 b0, const u32 b1) {
    asm volatile(
        "mma.sync.aligned.m16n8k16.row.col.f32.f16.f16.f32 "
        "{%0,%1,%2,%3}, {%4,%5,%6,%7}, {%8,%9}, {%0,%1,%2,%3};"
        : "+f"(d[0]), "+f"(d[1]), "+f"(d[2]), "+f"(d[3])
        : "r"(a0), "r"(a1), "r"(a2), "r"(a3), "r"(b0), "r"(b1));
}
// packed u16 index for B-style images: element (b, k), hi part (+4 for lo)
__device__ __forceinline__ int bpk_idx(int b, int k) {
    return ((((b >> 3) * NKC + (k >> 4)) * 32 + 4 * (b & 7) + ((k & 7) >> 1)) << 3)
           + (((k >> 3) & 1) << 1) + (k & 1);
}

// ---------------- barriers ----------------
__device__ __forceinline__ void gbarf(unsigned& ep) {
    __syncthreads();
    ep += 1;
    if (threadIdx.x == 0) {
        unsigned tgt = ep * (unsigned)gridDim.x;
        __threadfence();
        atomicAdd((unsigned*)&g_arrive, 1u);
        while ((int)(g_arrive - tgt) < 0) __nanosleep(32);
        __threadfence();
    }
    __syncthreads();
}
__device__ __forceinline__ void gbar_final() {
    __syncthreads();
    if (threadIdx.x == 0) {
        unsigned gen = g_gen;
        __threadfence();
        if (atomicAdd(&g_cnt, 1u) == gridDim.x - 1) {
            g_cnt = 0;
            g_arrive = 0;
            __threadfence();
            g_gen = gen + 1;
        } else {
            while (g_gen == gen) __nanosleep(32);
        }
        __threadfence();
    }
    __syncthreads();
}

// ---------------- block unit: 256 rows x 64 b over k16 chunks [kb0,kb1) ----------------
// B k-range staged into smem; A (fp16 W) register double-buffered. 2-term fp16 MMA, term-major.
__device__ __forceinline__ void tc_unit(const u16* __restrict__ Wh,
                                        const u16* __restrict__ Bpk, uint4* __restrict__ sB4,
                                        float* __restrict__ dst,
                                        int rowbase, int kb0, int kb1, int tid, int wid)
{
    const int nchunks = kb1 - kb0;

    // ---- stage B fragments for this k-range into smem (coalesced uint4) ----
    __syncthreads();    // previous unit's readers done before overwrite
    const uint4* Bp = (const uint4*)Bpk;
    for (int idx = tid; idx < nchunks * 256; idx += TPB) {
        int c = idx >> 8, r = idx & 255;
        int n = r >> 5, ln = r & 31;
        sB4[idx] = Bp[((size_t)n * NKC + kb0 + c) * 32 + ln];
    }
    __syncthreads();

    // ---- per-warp MMA: warp wid handles m16 tile rowbase/16 + wid ----
    const int lane = tid & 31;
    const int g = lane >> 2, t4 = lane & 3;
    const int mt = (rowbase >> 4) + wid;
    const uint4* Ah = (const uint4*)Wh;

    float d[8][4];
#pragma unroll
    for (int n = 0; n < 8; n++)
#pragma unroll
        for (int q = 0; q < 4; q++) d[n][q] = 0.f;

    const size_t abase = ((size_t)mt * NKC + kb0) * 32 + lane;
    uint4 ahc = Ah[abase];

    for (int c = 0; c < nchunks; c++) {
        uint4 ahn;
        if (c + 1 < nchunks)                // prefetch next A chunk before MMAs
            ahn = Ah[abase + (size_t)(c + 1) * 32];
        const uint4* bs = sB4 + c * 256 + lane;
        uint4 bp[8];
#pragma unroll
        for (int n = 0; n < 8; n++) bp[n] = bs[n * 32];
        // term-major: all 8 accumulators per term -> dependency distance 8
#pragma unroll
        for (int n = 0; n < 8; n++)
            mma_f16(d[n], ahc.x, ahc.y, ahc.z, ahc.w, bp[n].x, bp[n].y); // W*Xhi
#pragma unroll
        for (int n = 0; n < 8; n++)
            mma_f16(d[n], ahc.x, ahc.y, ahc.z, ahc.w, bp[n].z, bp[n].w); // W*Xlo
        ahc = ahn;
    }

    // ---- writeback ----
    int r = mt * 16 + g;
#pragma unroll
    for (int n = 0; n < 8; n++) {
        *(float2*)(dst + (size_t)r * 64 + n * 8 + 2 * t4)       = make_float2(d[n][0], d[n][1]);
        *(float2*)(dst + (size_t)(r + 8) * 64 + n * 8 + 2 * t4) = make_float2(d[n][2], d[n][3]);
    }
}

// ---------------- persistent kernel ----------------
__global__ void __launch_bounds__(TPB, 1) uni_kernel(
    const int*   __restrict__ xb,
    const float* __restrict__ h0,    const float* __restrict__ c0,
    const float* __restrict__ etab,
    const float* __restrict__ w_mx,  const float* __restrict__ w_mh,
    const float* __restrict__ w_ih,  const float* __restrict__ w_hm,
    const float* __restrict__ bias,
    const float* __restrict__ w_lin, const float* __restrict__ b_lin,
    float* __restrict__ out)
{
    extern __shared__ __align__(16) char dsm[];
    uint4* sB4 = (uint4*)dsm;          // B fragment staging (57 KB)
    float* s_proj = (float*)dsm;       // overlay for final projection
    __shared__ int s_tok[Bsz];

    const int tid = threadIdx.x;
    const int wid = tid >> 5;          // 0..15
    const int gid = blockIdx.x * TPB + tid;
    const int gstride = gridDim.x * TPB;
    unsigned ep = 0;

    // ================= pre phase A =================
    for (int i = gid; i < NTOK * Hdim; i += gstride) {
        int v = i / Hdim, j = i - v * Hdim;
        float a = 0.f;
        if (v != 0)
#pragma unroll
            for (int e = 0; e < Edim; e++)
                a = fmaf(etab[(size_t)v * Edim + e], w_mx[(size_t)j * Edim + e], a);
        g_mxtok[v][j] = a;
    }
    for (int i = gid; i < NTOK * Grows; i += gstride) {
        int v = i / Grows, r = i - v * Grows;
        float a = bias[r];
        if (v != 0)
#pragma unroll
            for (int e = 0; e < Edim; e++)
                a = fmaf(etab[(size_t)v * Edim + e], w_ih[(size_t)r * Edim + e], a);
        g_gxtok[v][r] = a;
    }
    for (int i = gid; i < HB; i += gstride) {
        int j = i >> 6, b = i & 63;
        g_cT[i] = c0[(size_t)b * Hdim + j];
    }
    for (int i = gid; i < 8 * NKC * 256; i += gstride) { g_hpk[i] = 0; g_xpk[i] = 0; }
    gbarf(ep);
    for (int i = gid; i < HB; i += gstride) {
        int j = i >> 6, b = i & 63;
        u16 hi, lo; hsplit(h0[(size_t)b * Hdim + j], hi, lo);
        int p = bpk_idx(b, j);
        g_hpk[p] = hi; g_hpk[p + 4] = lo;
    }
    for (int i = gid; i < R2P * Bsz; i += gstride) g_gpart[9][i] = 0.f;
    // W1 fragment-packed image (w_mh) — fp16 single image
    for (size_t i = gid; i < (size_t)A1T * NKC * 256; i += gstride) {
        int mt = (int)(i / (NKC * 256));
        int rem = (int)(i - (size_t)mt * (NKC * 256));
        int kc = rem >> 8, r2 = rem & 255;
        int lane = r2 >> 3, e = r2 & 7;
        int g = lane >> 2, t4 = lane & 3;
        int q = e >> 1, bit = e & 1;
        int row = mt * 16 + g + ((q & 1) ? 8 : 0);
        int col = kc * 16 + 2 * t4 + ((q & 2) ? 8 : 0) + bit;
        float v = (row < Hdim && col < Hdim) ? w_mh[(size_t)row * Hdim + col] : 0.f;
        g_w1h[i] = f2h(v);
    }
    // W2 fragment-packed image (w_hm) — fp16 single image; image row = gate*1920 + hj
    for (size_t i = gid; i < (size_t)A2T * NKC * 256; i += gstride) {
        int mt = (int)(i / (NKC * 256));
        int rem = (int)(i - (size_t)mt * (NKC * 256));
        int kc = rem >> 8, r2 = rem & 255;
        int lane = r2 >> 3, e = r2 & 7;
        int g = lane >> 2, t4 = lane & 3;
        int q = e >> 1, bit = e & 1;
        int row = mt * 16 + g + ((q & 1) ? 8 : 0);
        int col = kc * 16 + 2 * t4 + ((q & 2) ? 8 : 0) + bit;
        int gate = row / KP_GATE, hj = row - gate * KP_GATE;
        float v = 0.f;
        if (hj < Hdim && col < Hdim)
            v = w_hm[((size_t)gate * Hdim + hj) * Hdim + col];
        g_w2h[i] = f2h(v);
    }
    gbarf(ep);

    // ================= pre phase B: mxT =================
    for (int unit = blockIdx.x; unit < Lseq; unit += gridDim.x) {
        __syncthreads();
        if (tid < Bsz) s_tok[tid] = xb[(size_t)tid * Lseq + unit];
        __syncthreads();
        float* dst = g_mxT + (size_t)unit * HB;
        for (int i = tid; i < HB; i += TPB) {
            int j = i >> 6, b = i & 63;
            dst[i] = g_mxtok[s_tok[b]][j];
        }
    }
    gbarf(ep);

    // ================= recurrent loop =================
    for (int t = 0; t < Lseq; t++) {
        // ---- P1: mdot partials = w_mh @ h (144 units: 8 rowtiles x 18 ksplits) ----
        for (int u = blockIdx.x; u < NU1; u += gridDim.x) {
            int rt = u / P1KS, ks = u - rt * P1KS;
            int kb0 = (ks * NKC) / P1KS, kb1 = ((ks + 1) * NKC) / P1KS;
            tc_unit(g_w1h, g_hpk, sB4, g_m1part[ks],
                    rt * 256, kb0, kb1, tid, wid);
        }
        gbarf(ep);

        // ---- P1.5: reduce partials, x2 = mdot*mx, scatter into packed x image ----
        {
            const float4* mx4 = (const float4*)(g_mxT + (size_t)t * HB);
            for (int i = gid; i < HB / 4; i += gstride) {
                float4 s = ((const float4*)g_m1part[0])[i];
#pragma unroll
                for (int ks = 1; ks < P1KS; ks++) {
                    float4 p = ((const float4*)g_m1part[ks])[i];
                    s.x += p.x; s.y += p.y; s.z += p.z; s.w += p.w;
                }
                float4 m = mx4[i];
                s.x *= m.x; s.y *= m.y; s.z *= m.z; s.w *= m.w;
                int j = i >> 4, b0 = (i & 15) * 4;
                const float* ps = (const float*)&s;
#pragma unroll
                for (int q = 0; q < 4; q++) {
                    u16 hi, lo; hsplit(ps[q], hi, lo);
                    int p = bpk_idx(b0 + q, j);
                    g_xpk[p] = hi; g_xpk[p + 4] = lo;
                }
            }
        }
        gbarf(ep);

        // ---- P2: gate partials = w_hm @ x2 (296 ragged units over 30 rowtiles) ----
        for (int u = blockIdx.x; u < NU2; u += gridDim.x) {
            int ks = u / 30, rt = u - ks * 30;
            int nks = (rt < 26) ? 10 : 9;
            int kb0 = (ks * NKC) / nks, kb1 = ((ks + 1) * NKC) / nks;
            tc_unit(g_w2h, g_xpk, sB4, g_gpart[ks],
                    rt * 256, kb0, kb1, tid, wid);
        }
        gbarf(ep);

        // ---- P3: gates + c/h update + hs + packed h scatter ----
        {
            __syncthreads();
            if (tid < Bsz) s_tok[tid] = xb[(size_t)tid * Lseq + t];
            __syncthreads();
            float* hs = g_hsT + (size_t)t * HB;
            for (int i = gid; i < HB / 4; i += gstride) {
                int hj = i >> 4, b0 = (i & 15) * 4;
                float4 gv[4];
#pragma unroll
                for (int gg = 0; gg < 4; gg++) {
                    int r = gg * KP_GATE + hj;
                    float4 a;
                    a.x = g_gxtok[s_tok[b0]][gg * Hdim + hj];
                    a.y = g_gxtok[s_tok[b0 + 1]][gg * Hdim + hj];
                    a.z = g_gxtok[s_tok[b0 + 2]][gg * Hdim + hj];
                    a.w = g_gxtok[s_tok[b0 + 3]][gg * Hdim + hj];
#pragma unroll
                    for (int ks = 0; ks < 10; ks++) {
                        float4 p = *(const float4*)(g_gpart[ks] + (size_t)r * 64 + b0);
                        a.x += p.x; a.y += p.y; a.z += p.z; a.w += p.w;
                    }
                    gv[gg] = a;
                }
                float4 c4 = ((const float4*)g_cT)[i];
                float4 h4;
                const float* pi = (const float*)&gv[0];
                const float* pf = (const float*)&gv[1];
                const float* pg = (const float*)&gv[2];
                const float* po = (const float*)&gv[3];
                float* pc = (float*)&c4;
                float* ph = (float*)&h4;
#pragma unroll
                for (int q = 0; q < 4; q++) {
                    float si = __fdividef(1.f, 1.f + __expf(-pi[q]));
                    float sf = __fdividef(1.f, 1.f + __expf(-pf[q]));
                    float so = __fdividef(1.f, 1.f + __expf(-po[q]));
                    float c = sf * pc[q] + si * tanhf(pg[q]);
                    pc[q] = c;
                    float h = so * tanhf(c);
                    ph[q] = h;
                    u16 hi, lo; hsplit(h, hi, lo);
                    int p = bpk_idx(b0 + q, hj);
                    g_hpk[p] = hi; g_hpk[p + 4] = lo;
                }
                ((float4*)g_cT)[i] = c4;
                ((float4*)hs)[i] = h4;
            }
        }
        gbarf(ep);
    }
    gbar_final();

    // ================= final projection =================
    for (int unit = blockIdx.x; unit < Lseq; unit += gridDim.x) {
        const float* X = g_hsT + (size_t)unit * HB;
        float acc[4];
#pragma unroll
        for (int q = 0; q < 4; q++) acc[q] = 0.f;
        int b = tid & 63, ng = tid >> 6;   // ng 0..7
        for (int kt = 0; kt < 60; kt++) {
            int k0 = kt * 32;
            __syncthreads();
#pragma unroll
            for (int u = 0; u < 4; u++) {
                int idx = u * TPB + tid;
                int k = k0 + (idx >> 6);
                s_proj[idx] = (k < Hdim) ? X[(size_t)k0 * 64 + idx] : 0.f;
            }
            __syncthreads();
            int klim = Hdim - k0; if (klim > 32) klim = 32;
            for (int kk = 0; kk < klim; kk++) {
                float xv = s_proj[kk * 64 + b];
#pragma unroll
                for (int q = 0; q < 4; q++) {
                    int n = ng + q * 8;
                    if (n < NOUT) acc[q] = fmaf(xv, w_lin[(size_t)n * Hdim + k0 + kk], acc[q]);
                }
            }
        }
#pragma unroll
        for (int q = 0; q < 4; q++) {
            int n = ng + q * 8;
            if (n < NOUT)
                out[((size_t)b * Lseq + unit) * NOUT + n] = acc[q] + b_lin[n];
        }
    }
}

// ---------------- launcher: ONE graph node ----------------
extern "C" void kernel_launch(void* const* d_in, const int* in_sizes, int n_in,
                              void* d_out, int out_size)
{
    (void)in_sizes; (void)n_in; (void)out_size;
    const int*   xb    = (const int*)  d_in[0];
    // d_in[1] = xb_lens (unused by the reference math)
    const float* h0    = (const float*)d_in[2];
    const float* c0    = (const float*)d_in[3];
    const float* etab  = (const float*)d_in[4];
    const float* w_mx  = (const float*)d_in[5];
    const float* w_mh  = (const float*)d_in[6];
    const float* w_ih  = (const float*)d_in[7];
    const float* w_hm  = (const float*)d_in[8];
    const float* bias  = (const float*)d_in[9];
    const float* w_lin = (const float*)d_in[10];
    const float* b_lin = (const float*)d_in[11];
    float* out = (float*)d_out;

    static int smem_set = 0;
    if (!smem_set) {
        cudaFuncSetAttribute(uni_kernel, cudaFuncAttributeMaxDynamicSharedMemorySize, SMEM_BYTES);
        smem_set = 1;
    }

    int sms = 0;
    if (cudaDeviceGetAttribute(&sms, cudaDevAttrMultiProcessorCount, 0) != cudaSuccess || sms <= 0)
        sms = 148;

    uni_kernel<<<sms, TPB, SMEM_BYTES>>>(xb, h0, c0, etab, w_mx, w_mh, w_ih, w_hm,
                                         bias, w_lin, b_lin, out);
}

// round 16
// speedup vs baseline: 1.7293x; 1.1945x over previous
#include <cuda_runtime.h>
#include <cuda_fp16.h>
#include <math.h>
#include <stdint.h>

#define Bsz   64
#define Lseq  512
#define Edim  10
#define Hdim  1900
#define Grows 7600
#define NOUT  25
#define TPB   512
#define NTOK  30
#define KP_GATE 1920          // gate stride (rows) in W2 image space
#define NKC   119             // k16 chunks covering 1900
#define R1P   2048            // padded rows, W1 image space (8 rowtiles x 256)
#define R2P   7680            // padded rows, W2 image space (30 rowtiles x 256)
#define A1T   (R1P / 16)      // 128 m16 tiles
#define A2T   (R2P / 16)      // 480 m16 tiles
#define P1KS  18
#define NU1   (8 * P1KS)      // 144
#define NU2   296
#define HB    (Hdim * Bsz)    // 121600
#define NCMAX 14              // max k16 chunks per unit
#define SMEM_BYTES (NCMAX * 256 * 8)   // 28672 B: staged B fragments (uint2 per lane)

typedef unsigned int u32;
typedef unsigned short u16;

// ---------------- scratch (__device__ globals; no allocations) ----------------
static __device__ float g_mxT[(size_t)Lseq * HB];
static __device__ float g_hsT[(size_t)Lseq * HB];
static __device__ float g_cT[HB];
static __device__ float g_m1part[P1KS][R1P * Bsz];            // P1 k-split partials [row][b]
static __device__ float g_gpart[10][R2P * Bsz];               // P2 k-split partials [row][b]
static __device__ float g_mxtok[NTOK][Hdim];
static __device__ float g_gxtok[NTOK][Grows];
// fragment-packed operand images (u16 = fp16 bits), layout [tile][kc][lane][...]
static __device__ __align__(16) u16 g_w1h[(size_t)A1T * NKC * 256];   // w_mh fp16 (8 u16/lane)
static __device__ __align__(16) u16 g_w2h[(size_t)A2T * NKC * 256];   // w_hm fp16 (8 u16/lane)
static __device__ __align__(16) u16 g_hpk[8 * NKC * 128];     // h fp16 (4 u16/lane)
static __device__ __align__(16) u16 g_xpk[8 * NKC * 128];     // x2 fp16 (4 u16/lane)
static __device__ volatile unsigned g_arrive;
static __device__ unsigned g_cnt;
static __device__ volatile unsigned g_gen;

// ---------------- helpers ----------------
__device__ __forceinline__ u16 f2h(float v) {
    __half h = __float2half_rn(v);
    return *reinterpret_cast<u16*>(&h);
}
__device__ __forceinline__ void mma_f16(float d[4], const u32 a0, const u32 a1, const u32 a2, const u32 a3,
                                        const u32 b0, const u32 b1) {
    asm volatile(
        "mma.sync.aligned.m16n8k16.row.col.f32.f16.f16.f32 "
        "{%0,%1,%2,%3}, {%4,%5,%6,%7}, {%8,%9}, {%0,%1,%2,%3};"
        : "+f"(d[0]), "+f"(d[1]), "+f"(d[2]), "+f"(d[3])
        : "r"(a0), "r"(a1), "r"(a2), "r"(a3), "r"(b0), "r"(b1));
}
// packed u16 index for B-style images (4 u16 per lane slot): element (b, k)
__device__ __forceinline__ int bpk_idx(int b, int k) {
    return ((((b >> 3) * NKC + (k >> 4)) * 32 + 4 * (b & 7) + ((k & 7) >> 1)) << 2)
           + (((k >> 3) & 1) << 1) + (k & 1);
}

// ---------------- barriers ----------------
__device__ __forceinline__ void gbarf(unsigned& ep) {
    __syncthreads();
    ep += 1;
    if (threadIdx.x == 0) {
        unsigned tgt = ep * (unsigned)gridDim.x;
        __threadfence();
        atomicAdd((unsigned*)&g_arrive, 1u);
        while ((int)(g_arrive - tgt) < 0) __nanosleep(32);
        __threadfence();
    }
    __syncthreads();
}
__device__ __forceinline__ void gbar_final() {
    __syncthreads();
    if (threadIdx.x == 0) {
        unsigned gen = g_gen;
        __threadfence();
        if (atomicAdd(&g_cnt, 1u) == gridDim.x - 1) {
            g_cnt = 0;
            g_arrive = 0;
            __threadfence();
            g_gen = gen + 1;
        } else {
            while (g_gen == gen) __nanosleep(32);
        }
        __threadfence();
    }
    __syncthreads();
}

// ---------------- block unit: 256 rows x 64 b over k16 chunks [kb0,kb1) ----------------
// B k-range staged into smem (uint2/lane); A (fp16 W) register double-buffered. 1-term fp16 MMA.
__device__ __forceinline__ void tc_unit(const u16* __restrict__ Wh,
                                        const u16* __restrict__ Bpk, uint2* __restrict__ sB2,
                                        float* __restrict__ dst,
                                        int rowbase, int kb0, int kb1, int tid, int wid)
{
    const int nchunks = kb1 - kb0;

    // ---- stage B fragments for this k-range into smem (coalesced uint2) ----
    __syncthreads();    // previous unit's readers done before overwrite
    const uint2* Bp = (const uint2*)Bpk;
    for (int idx = tid; idx < nchunks * 256; idx += TPB) {
        int c = idx >> 8, r = idx & 255;
        int n = r >> 5, ln = r & 31;
        sB2[idx] = Bp[((size_t)n * NKC + kb0 + c) * 32 + ln];
    }
    __syncthreads();

    // ---- per-warp MMA: warp wid handles m16 tile rowbase/16 + wid ----
    const int lane = tid & 31;
    const int g = lane >> 2, t4 = lane & 3;
    const int mt = (rowbase >> 4) + wid;
    const uint4* Ah = (const uint4*)Wh;

    float d[8][4];
#pragma unroll
    for (int n = 0; n < 8; n++)
#pragma unroll
        for (int q = 0; q < 4; q++) d[n][q] = 0.f;

    const size_t abase = ((size_t)mt * NKC + kb0) * 32 + lane;
    uint4 ahc = Ah[abase];

    for (int c = 0; c < nchunks; c++) {
        uint4 ahn;
        if (c + 1 < nchunks)                // prefetch next A chunk before MMAs
            ahn = Ah[abase + (size_t)(c + 1) * 32];
        const uint2* bs = sB2 + c * 256 + lane;
        uint2 bp[8];
#pragma unroll
        for (int n = 0; n < 8; n++) bp[n] = bs[n * 32];
#pragma unroll
        for (int n = 0; n < 8; n++)
            mma_f16(d[n], ahc.x, ahc.y, ahc.z, ahc.w, bp[n].x, bp[n].y); // W*X
        ahc = ahn;
    }

    // ---- writeback ----
    int r = mt * 16 + g;
#pragma unroll
    for (int n = 0; n < 8; n++) {
        *(float2*)(dst + (size_t)r * 64 + n * 8 + 2 * t4)       = make_float2(d[n][0], d[n][1]);
        *(float2*)(dst + (size_t)(r + 8) * 64 + n * 8 + 2 * t4) = make_float2(d[n][2], d[n][3]);
    }
}

// ---------------- persistent kernel ----------------
__global__ void __launch_bounds__(TPB, 1) uni_kernel(
    const int*   __restrict__ xb,
    const float* __restrict__ h0,    const float* __restrict__ c0,
    const float* __restrict__ etab,
    const float* __restrict__ w_mx,  const float* __restrict__ w_mh,
    const float* __restrict__ w_ih,  const float* __restrict__ w_hm,
    const float* __restrict__ bias,
    const float* __restrict__ w_lin, const float* __restrict__ b_lin,
    float* __restrict__ out)
{
    extern __shared__ __align__(16) char dsm[];
    uint2* sB2 = (uint2*)dsm;          // B fragment staging (28 KB)
    float* s_proj = (float*)dsm;       // overlay for final projection
    __shared__ int s_tok[Bsz];

    const int tid = threadIdx.x;
    const int wid = tid >> 5;          // 0..15
    const int gid = blockIdx.x * TPB + tid;
    const int gstride = gridDim.x * TPB;
    unsigned ep = 0;

    // ================= pre phase A =================
    for (int i = gid; i < NTOK * Hdim; i += gstride) {
        int v = i / Hdim, j = i - v * Hdim;
        float a = 0.f;
        if (v != 0)
#pragma unroll
            for (int e = 0; e < Edim; e++)
                a = fmaf(etab[(size_t)v * Edim + e], w_mx[(size_t)j * Edim + e], a);
        g_mxtok[v][j] = a;
    }
    for (int i = gid; i < NTOK * Grows; i += gstride) {
        int v = i / Grows, r = i - v * Grows;
        float a = bias[r];
        if (v != 0)
#pragma unroll
            for (int e = 0; e < Edim; e++)
                a = fmaf(etab[(size_t)v * Edim + e], w_ih[(size_t)r * Edim + e], a);
        g_gxtok[v][r] = a;
    }
    for (int i = gid; i < HB; i += gstride) {
        int j = i >> 6, b = i & 63;
        g_cT[i] = c0[(size_t)b * Hdim + j];
    }
    for (int i = gid; i < 8 * NKC * 128; i += gstride) { g_hpk[i] = 0; g_xpk[i] = 0; }
    gbarf(ep);
    for (int i = gid; i < HB; i += gstride) {
        int j = i >> 6, b = i & 63;
        g_hpk[bpk_idx(b, j)] = f2h(h0[(size_t)b * Hdim + j]);
    }
    for (int i = gid; i < R2P * Bsz; i += gstride) g_gpart[9][i] = 0.f;
    // W1 fragment-packed image (w_mh) — fp16 single image
    for (size_t i = gid; i < (size_t)A1T * NKC * 256; i += gstride) {
        int mt = (int)(i / (NKC * 256));
        int rem = (int)(i - (size_t)mt * (NKC * 256));
        int kc = rem >> 8, r2 = rem & 255;
        int lane = r2 >> 3, e = r2 & 7;
        int g = lane >> 2, t4 = lane & 3;
        int q = e >> 1, bit = e & 1;
        int row = mt * 16 + g + ((q & 1) ? 8 : 0);
        int col = kc * 16 + 2 * t4 + ((q & 2) ? 8 : 0) + bit;
        float v = (row < Hdim && col < Hdim) ? w_mh[(size_t)row * Hdim + col] : 0.f;
        g_w1h[i] = f2h(v);
    }
    // W2 fragment-packed image (w_hm) — fp16 single image; image row = gate*1920 + hj
    for (size_t i = gid; i < (size_t)A2T * NKC * 256; i += gstride) {
        int mt = (int)(i / (NKC * 256));
        int rem = (int)(i - (size_t)mt * (NKC * 256));
        int kc = rem >> 8, r2 = rem & 255;
        int lane = r2 >> 3, e = r2 & 7;
        int g = lane >> 2, t4 = lane & 3;
        int q = e >> 1, bit = e & 1;
        int row = mt * 16 + g + ((q & 1) ? 8 : 0);
        int col = kc * 16 + 2 * t4 + ((q & 2) ? 8 : 0) + bit;
        int gate = row / KP_GATE, hj = row - gate * KP_GATE;
        float v = 0.f;
        if (hj < Hdim && col < Hdim)
            v = w_hm[((size_t)gate * Hdim + hj) * Hdim + col];
        g_w2h[i] = f2h(v);
    }
    gbarf(ep);

    // ================= pre phase B: mxT =================
    for (int unit = blockIdx.x; unit < Lseq; unit += gridDim.x) {
        __syncthreads();
        if (tid < Bsz) s_tok[tid] = xb[(size_t)tid * Lseq + unit];
        __syncthreads();
        float* dst = g_mxT + (size_t)unit * HB;
        for (int i = tid; i < HB; i += TPB) {
            int j = i >> 6, b = i & 63;
            dst[i] = g_mxtok[s_tok[b]][j];
        }
    }
    gbarf(ep);

    // ================= recurrent loop =================
    for (int t = 0; t < Lseq; t++) {
        // ---- P1: mdot partials = w_mh @ h (144 units: 8 rowtiles x 18 ksplits) ----
        for (int u = blockIdx.x; u < NU1; u += gridDim.x) {
            int rt = u / P1KS, ks = u - rt * P1KS;
            int kb0 = (ks * NKC) / P1KS, kb1 = ((ks + 1) * NKC) / P1KS;
            tc_unit(g_w1h, g_hpk, sB2, g_m1part[ks],
                    rt * 256, kb0, kb1, tid, wid);
        }
        gbarf(ep);

        // ---- P1.5: reduce partials, x2 = mdot*mx, scatter into packed x image ----
        {
            const float4* mx4 = (const float4*)(g_mxT + (size_t)t * HB);
            for (int i = gid; i < HB / 4; i += gstride) {
                float4 s = ((const float4*)g_m1part[0])[i];
#pragma unroll
                for (int ks = 1; ks < P1KS; ks++) {
                    float4 p = ((const float4*)g_m1part[ks])[i];
                    s.x += p.x; s.y += p.y; s.z += p.z; s.w += p.w;
                }
                float4 m = mx4[i];
                s.x *= m.x; s.y *= m.y; s.z *= m.z; s.w *= m.w;
                int j = i >> 4, b0 = (i & 15) * 4;
                const float* ps = (const float*)&s;
#pragma unroll
                for (int q = 0; q < 4; q++)
                    g_xpk[bpk_idx(b0 + q, j)] = f2h(ps[q]);
            }
        }
        gbarf(ep);

        // ---- P2: gate partials = w_hm @ x2 (296 ragged units over 30 rowtiles) ----
        for (int u = blockIdx.x; u < NU2; u += gridDim.x) {
            int ks = u / 30, rt = u - ks * 30;
            int nks = (rt < 26) ? 10 : 9;
            int kb0 = (ks * NKC) / nks, kb1 = ((ks + 1) * NKC) / nks;
            tc_unit(g_w2h, g_xpk, sB2, g_gpart[ks],
                    rt * 256, kb0, kb1, tid, wid);
        }
        gbarf(ep);

        // ---- P3: gates + c/h update + hs + packed h scatter ----
        {
            __syncthreads();
            if (tid < Bsz) s_tok[tid] = xb[(size_t)tid * Lseq + t];
            __syncthreads();
            float* hs = g_hsT + (size_t)t * HB;
            for (int i = gid; i < HB / 4; i += gstride) {
                int hj = i >> 4, b0 = (i & 15) * 4;
                float4 gv[4];
#pragma unroll
                for (int gg = 0; gg < 4; gg++) {
                    int r = gg * KP_GATE + hj;
                    float4 a;
                    a.x = g_gxtok[s_tok[b0]][gg * Hdim + hj];
                    a.y = g_gxtok[s_tok[b0 + 1]][gg * Hdim + hj];
                    a.z = g_gxtok[s_tok[b0 + 2]][gg * Hdim + hj];
                    a.w = g_gxtok[s_tok[b0 + 3]][gg * Hdim + hj];
#pragma unroll
                    for (int ks = 0; ks < 10; ks++) {
                        float4 p = *(const float4*)(g_gpart[ks] + (size_t)r * 64 + b0);
                        a.x += p.x; a.y += p.y; a.z += p.z; a.w += p.w;
                    }
                    gv[gg] = a;
                }
                float4 c4 = ((const float4*)g_cT)[i];
                float4 h4;
                const float* pi = (const float*)&gv[0];
                const float* pf = (const float*)&gv[1];
                const float* pg = (const float*)&gv[2];
                const float* po = (const float*)&gv[3];
                float* pc = (float*)&c4;
                float* ph = (float*)&h4;
#pragma unroll
                for (int q = 0; q < 4; q++) {
                    float si = __fdividef(1.f, 1.f + __expf(-pi[q]));
                    float sf = __fdividef(1.f, 1.f + __expf(-pf[q]));
                    float so = __fdividef(1.f, 1.f + __expf(-po[q]));
                    float c = sf * pc[q] + si * tanhf(pg[q]);
                    pc[q] = c;
                    float h = so * tanhf(c);
                    ph[q] = h;
                    g_hpk[bpk_idx(b0 + q, hj)] = f2h(h);
                }
                ((float4*)g_cT)[i] = c4;
                ((float4*)hs)[i] = h4;
            }
        }
        gbarf(ep);
    }
    gbar_final();

    // ================= final projection =================
    for (int unit = blockIdx.x; unit < Lseq; unit += gridDim.x) {
        const float* X = g_hsT + (size_t)unit * HB;
        float acc[4];
#pragma unroll
        for (int q = 0; q < 4; q++) acc[q] = 0.f;
        int b = tid & 63, ng = tid >> 6;   // ng 0..7
        for (int kt = 0; kt < 60; kt++) {
            int k0 = kt * 32;
            __syncthreads();
#pragma unroll
            for (int u = 0; u < 4; u++) {
                int idx = u * TPB + tid;
                int k = k0 + (idx >> 6);
                s_proj[idx] = (k < Hdim) ? X[(size_t)k0 * 64 + idx] : 0.f;
            }
            __syncthreads();
            int klim = Hdim - k0; if (klim > 32) klim = 32;
            for (int kk = 0; kk < klim; kk++) {
                float xv = s_proj[kk * 64 + b];
#pragma unroll
                for (int q = 0; q < 4; q++) {
                    int n = ng + q * 8;
                    if (n < NOUT) acc[q] = fmaf(xv, w_lin[(size_t)n * Hdim + k0 + kk], acc[q]);
                }
            }
        }
#pragma unroll
        for (int q = 0; q < 4; q++) {
            int n = ng + q * 8;
            if (n < NOUT)
                out[((size_t)b * Lseq + unit) * NOUT + n] = acc[q] + b_lin[n];
        }
    }
}

// ---------------- launcher: ONE graph node ----------------
extern "C" void kernel_launch(void* const* d_in, const int* in_sizes, int n_in,
                              void* d_out, int out_size)
{
    (void)in_sizes; (void)n_in; (void)out_size;
    const int*   xb    = (const int*)  d_in[0];
    // d_in[1] = xb_lens (unused by the reference math)
    const float* h0    = (const float*)d_in[2];
    const float* c0    = (const float*)d_in[3];
    const float* etab  = (const float*)d_in[4];
    const float* w_mx  = (const float*)d_in[5];
    const float* w_mh  = (const float*)d_in[6];
    const float* w_ih  = (const float*)d_in[7];
    const float* w_hm  = (const float*)d_in[8];
    const float* bias  = (const float*)d_in[9];
    const float* w_lin = (const float*)d_in[10];
    const float* b_lin = (const float*)d_in[11];
    float* out = (float*)d_out;

    static int smem_set = 0;
    if (!smem_set) {
        cudaFuncSetAttribute(uni_kernel, cudaFuncAttributeMaxDynamicSharedMemorySize, SMEM_BYTES);
        smem_set = 1;
    }

    int sms = 0;
    if (cudaDeviceGetAttribute(&sms, cudaDevAttrMultiProcessorCount, 0) != cudaSuccess || sms <= 0)
        sms = 148;

    uni_kernel<<<sms, TPB, SMEM_BYTES>>>(xb, h0, c0, etab, w_mx, w_mh, w_ih, w_hm,
                                         bias, w_lin, b_lin, out);
}

// round 17
// speedup vs baseline: 1.8028x; 1.0425x over previous
#include <cuda_runtime.h>
#include <cuda_fp16.h>
#include <math.h>
#include <stdint.h>

#define Bsz   64
#define Lseq  512
#define Edim  10
#define Hdim  1900
#define Grows 7600
#define NOUT  25
#define TPB   512
#define NTOK  30
#define KP_GATE 1920          // gate stride (rows) in W2 image space
#define NKC   119             // k16 chunks covering 1900
#define R1P   2048            // padded rows, W1 image space (8 rowtiles x 256)
#define R2P   7680            // padded rows, W2 image space (30 rowtiles x 256)
#define A1T   (R1P / 16)      // 128 m16 tiles
#define A2T   (R2P / 16)      // 480 m16 tiles
#define P1KS  18
#define NU1   (8 * P1KS)      // 144
#define NU2   296
#define HB    (Hdim * Bsz)    // 121600
#define NCMAX 14              // max k16 chunks per unit
#define SMEM_BYTES (NCMAX * 256 * 8)   // 28672 B: staged B fragments (uint2 per lane)

typedef unsigned int u32;
typedef unsigned short u16;

// ---------------- scratch (__device__ globals; no allocations) ----------------
static __device__ float g_mxT[(size_t)Lseq * HB];
static __device__ float g_hsT[(size_t)Lseq * HB];
static __device__ float g_cT[HB];
static __device__ __align__(16) u16 g_m1part[P1KS][R1P * Bsz];   // P1 partials, fp16 [row][b]
static __device__ __align__(16) u16 g_gpart[10][R2P * Bsz];      // P2 partials, fp16 [row][b]
static __device__ float g_mxtok[NTOK][Hdim];
static __device__ float g_gxtok[NTOK][Grows];
// fragment-packed operand images (u16 = fp16 bits), layout [tile][kc][lane][...]
static __device__ __align__(16) u16 g_w1h[(size_t)A1T * NKC * 256];   // w_mh fp16 (8 u16/lane)
static __device__ __align__(16) u16 g_w2h[(size_t)A2T * NKC * 256];   // w_hm fp16 (8 u16/lane)
static __device__ __align__(16) u16 g_hpk[8 * NKC * 128];     // h fp16 (4 u16/lane)
static __device__ __align__(16) u16 g_xpk[8 * NKC * 128];     // x2 fp16 (4 u16/lane)
static __device__ volatile unsigned g_arrive;
static __device__ unsigned g_cnt;
static __device__ volatile unsigned g_gen;

// ---------------- helpers ----------------
__device__ __forceinline__ u16 f2h(float v) {
    __half h = __float2half_rn(v);
    return *reinterpret_cast<u16*>(&h);
}
__device__ __forceinline__ u32 pack2h(float a, float b) {
    __half2 h = __floats2half2_rn(a, b);
    return *reinterpret_cast<u32*>(&h);
}
__device__ __forceinline__ float2 unp2h(u32 v) {
    __half2 h = *reinterpret_cast<__half2*>(&v);
    return __half22float2(h);
}
__device__ __forceinline__ void mma_f16(float d[4], const u32 a0, const u32 a1, const u32 a2, const u32 a3,
                                        const u32 b0, const u32 b1) {
    asm volatile(
        "mma.sync.aligned.m16n8k16.row.col.f32.f16.f16.f32 "
        "{%0,%1,%2,%3}, {%4,%5,%6,%7}, {%8,%9}, {%0,%1,%2,%3};"
        : "+f"(d[0]), "+f"(d[1]), "+f"(d[2]), "+f"(d[3])
        : "r"(a0), "r"(a1), "r"(a2), "r"(a3), "r"(b0), "r"(b1));
}
// packed u16 index for B-style images (4 u16 per lane slot): element (b, k)
__device__ __forceinline__ int bpk_idx(int b, int k) {
    return ((((b >> 3) * NKC + (k >> 4)) * 32 + 4 * (b & 7) + ((k & 7) >> 1)) << 2)
           + (((k >> 3) & 1) << 1) + (k & 1);
}

// ---------------- barriers ----------------
__device__ __forceinline__ void gbarf(unsigned& ep) {
    __syncthreads();
    ep += 1;
    if (threadIdx.x == 0) {
        unsigned tgt = ep * (unsigned)gridDim.x;
        __threadfence();
        atomicAdd((unsigned*)&g_arrive, 1u);
        while ((int)(g_arrive - tgt) < 0) __nanosleep(32);
        __threadfence();
    }
    __syncthreads();
}
__device__ __forceinline__ void gbar_final() {
    __syncthreads();
    if (threadIdx.x == 0) {
        unsigned gen = g_gen;
        __threadfence();
        if (atomicAdd(&g_cnt, 1u) == gridDim.x - 1) {
            g_cnt = 0;
            g_arrive = 0;
            __threadfence();
            g_gen = gen + 1;
        } else {
            while (g_gen == gen) __nanosleep(32);
        }
        __threadfence();
    }
    __syncthreads();
}

// ---------------- block unit: 256 rows x 64 b over k16 chunks [kb0,kb1) ----------------
// B k-range staged into smem (uint2/lane); A (fp16 W) register double-buffered. 1-term fp16 MMA.
// Partial results stored as fp16 half2.
__device__ __forceinline__ void tc_unit(const u16* __restrict__ Wh,
                                        const u16* __restrict__ Bpk, uint2* __restrict__ sB2,
                                        u16* __restrict__ dst,
                                        int rowbase, int kb0, int kb1, int tid, int wid)
{
    const int nchunks = kb1 - kb0;

    // ---- stage B fragments for this k-range into smem (coalesced uint2) ----
    __syncthreads();    // previous unit's readers done before overwrite
    const uint2* Bp = (const uint2*)Bpk;
    for (int idx = tid; idx < nchunks * 256; idx += TPB) {
        int c = idx >> 8, r = idx & 255;
        int n = r >> 5, ln = r & 31;
        sB2[idx] = Bp[((size_t)n * NKC + kb0 + c) * 32 + ln];
    }
    __syncthreads();

    // ---- per-warp MMA: warp wid handles m16 tile rowbase/16 + wid ----
    const int lane = tid & 31;
    const int g = lane >> 2, t4 = lane & 3;
    const int mt = (rowbase >> 4) + wid;
    const uint4* Ah = (const uint4*)Wh;

    float d[8][4];
#pragma unroll
    for (int n = 0; n < 8; n++)
#pragma unroll
        for (int q = 0; q < 4; q++) d[n][q] = 0.f;

    const size_t abase = ((size_t)mt * NKC + kb0) * 32 + lane;
    uint4 ahc = Ah[abase];

    for (int c = 0; c < nchunks; c++) {
        uint4 ahn;
        if (c + 1 < nchunks)                // prefetch next A chunk before MMAs
            ahn = Ah[abase + (size_t)(c + 1) * 32];
        const uint2* bs = sB2 + c * 256 + lane;
        uint2 bp[8];
#pragma unroll
        for (int n = 0; n < 8; n++) bp[n] = bs[n * 32];
#pragma unroll
        for (int n = 0; n < 8; n++)
            mma_f16(d[n], ahc.x, ahc.y, ahc.z, ahc.w, bp[n].x, bp[n].y); // W*X
        ahc = ahn;
    }

    // ---- writeback (fp16 half2) ----
    int r = mt * 16 + g;
#pragma unroll
    for (int n = 0; n < 8; n++) {
        *(u32*)(dst + (size_t)r * 64 + n * 8 + 2 * t4)       = pack2h(d[n][0], d[n][1]);
        *(u32*)(dst + (size_t)(r + 8) * 64 + n * 8 + 2 * t4) = pack2h(d[n][2], d[n][3]);
    }
}

// ---------------- persistent kernel ----------------
__global__ void __launch_bounds__(TPB, 1) uni_kernel(
    const int*   __restrict__ xb,
    const float* __restrict__ h0,    const float* __restrict__ c0,
    const float* __restrict__ etab,
    const float* __restrict__ w_mx,  const float* __restrict__ w_mh,
    const float* __restrict__ w_ih,  const float* __restrict__ w_hm,
    const float* __restrict__ bias,
    const float* __restrict__ w_lin, const float* __restrict__ b_lin,
    float* __restrict__ out)
{
    extern __shared__ __align__(16) char dsm[];
    uint2* sB2 = (uint2*)dsm;          // B fragment staging (28 KB)
    float* s_proj = (float*)dsm;       // overlay for final projection
    __shared__ int s_tok[Bsz];

    const int tid = threadIdx.x;
    const int wid = tid >> 5;          // 0..15
    const int gid = blockIdx.x * TPB + tid;
    const int gstride = gridDim.x * TPB;
    unsigned ep = 0;

    // ================= pre phase A =================
    for (int i = gid; i < NTOK * Hdim; i += gstride) {
        int v = i / Hdim, j = i - v * Hdim;
        float a = 0.f;
        if (v != 0)
#pragma unroll
            for (int e = 0; e < Edim; e++)
                a = fmaf(etab[(size_t)v * Edim + e], w_mx[(size_t)j * Edim + e], a);
        g_mxtok[v][j] = a;
    }
    for (int i = gid; i < NTOK * Grows; i += gstride) {
        int v = i / Grows, r = i - v * Grows;
        float a = bias[r];
        if (v != 0)
#pragma unroll
            for (int e = 0; e < Edim; e++)
                a = fmaf(etab[(size_t)v * Edim + e], w_ih[(size_t)r * Edim + e], a);
        g_gxtok[v][r] = a;
    }
    for (int i = gid; i < HB; i += gstride) {
        int j = i >> 6, b = i & 63;
        g_cT[i] = c0[(size_t)b * Hdim + j];
    }
    for (int i = gid; i < 8 * NKC * 128; i += gstride) { g_hpk[i] = 0; g_xpk[i] = 0; }
    gbarf(ep);
    for (int i = gid; i < HB; i += gstride) {
        int j = i >> 6, b = i & 63;
        g_hpk[bpk_idx(b, j)] = f2h(h0[(size_t)b * Hdim + j]);
    }
    for (int i = gid; i < R2P * Bsz; i += gstride) g_gpart[9][i] = 0;
    // W1 fragment-packed image (w_mh) — fp16 single image
    for (size_t i = gid; i < (size_t)A1T * NKC * 256; i += gstride) {
        int mt = (int)(i / (NKC * 256));
        int rem = (int)(i - (size_t)mt * (NKC * 256));
        int kc = rem >> 8, r2 = rem & 255;
        int lane = r2 >> 3, e = r2 & 7;
        int g = lane >> 2, t4 = lane & 3;
        int q = e >> 1, bit = e & 1;
        int row = mt * 16 + g + ((q & 1) ? 8 : 0);
        int col = kc * 16 + 2 * t4 + ((q & 2) ? 8 : 0) + bit;
        float v = (row < Hdim && col < Hdim) ? w_mh[(size_t)row * Hdim + col] : 0.f;
        g_w1h[i] = f2h(v);
    }
    // W2 fragment-packed image (w_hm) — fp16 single image; image row = gate*1920 + hj
    for (size_t i = gid; i < (size_t)A2T * NKC * 256; i += gstride) {
        int mt = (int)(i / (NKC * 256));
        int rem = (int)(i - (size_t)mt * (NKC * 256));
        int kc = rem >> 8, r2 = rem & 255;
        int lane = r2 >> 3, e = r2 & 7;
        int g = lane >> 2, t4 = lane & 3;
        int q = e >> 1, bit = e & 1;
        int row = mt * 16 + g + ((q & 1) ? 8 : 0);
        int col = kc * 16 + 2 * t4 + ((q & 2) ? 8 : 0) + bit;
        int gate = row / KP_GATE, hj = row - gate * KP_GATE;
        float v = 0.f;
        if (hj < Hdim && col < Hdim)
            v = w_hm[((size_t)gate * Hdim + hj) * Hdim + col];
        g_w2h[i] = f2h(v);
    }
    gbarf(ep);

    // ================= pre phase B: mxT =================
    for (int unit = blockIdx.x; unit < Lseq; unit += gridDim.x) {
        __syncthreads();
        if (tid < Bsz) s_tok[tid] = xb[(size_t)tid * Lseq + unit];
        __syncthreads();
        float* dst = g_mxT + (size_t)unit * HB;
        for (int i = tid; i < HB; i += TPB) {
            int j = i >> 6, b = i & 63;
            dst[i] = g_mxtok[s_tok[b]][j];
        }
    }
    gbarf(ep);

    // ================= recurrent loop =================
    for (int t = 0; t < Lseq; t++) {
        // ---- P1: mdot partials = w_mh @ h (144 units: 8 rowtiles x 18 ksplits) ----
        for (int u = blockIdx.x; u < NU1; u += gridDim.x) {
            int rt = u / P1KS, ks = u - rt * P1KS;
            int kb0 = (ks * NKC) / P1KS, kb1 = ((ks + 1) * NKC) / P1KS;
            tc_unit(g_w1h, g_hpk, sB2, g_m1part[ks],
                    rt * 256, kb0, kb1, tid, wid);
        }
        gbarf(ep);

        // ---- P1.5: reduce fp16 partials, x2 = mdot*mx, scatter into packed x image ----
        {
            const float4* mx4 = (const float4*)(g_mxT + (size_t)t * HB);
            for (int i = gid; i < HB / 4; i += gstride) {
                float2 s01 = make_float2(0.f, 0.f), s23 = make_float2(0.f, 0.f);
#pragma unroll
                for (int ks = 0; ks < P1KS; ks++) {
                    uint2 v = ((const uint2*)g_m1part[ks])[i];
                    float2 f01 = unp2h(v.x), f23 = unp2h(v.y);
                    s01.x += f01.x; s01.y += f01.y; s23.x += f23.x; s23.y += f23.y;
                }
                float4 m = mx4[i];
                float r0 = s01.x * m.x, r1 = s01.y * m.y, r2 = s23.x * m.z, r3 = s23.y * m.w;
                int j = i >> 4, b0 = (i & 15) * 4;
                g_xpk[bpk_idx(b0,     j)] = f2h(r0);
                g_xpk[bpk_idx(b0 + 1, j)] = f2h(r1);
                g_xpk[bpk_idx(b0 + 2, j)] = f2h(r2);
                g_xpk[bpk_idx(b0 + 3, j)] = f2h(r3);
            }
        }
        gbarf(ep);

        // ---- P2: gate partials = w_hm @ x2 (296 ragged units over 30 rowtiles) ----
        for (int u = blockIdx.x; u < NU2; u += gridDim.x) {
            int ks = u / 30, rt = u - ks * 30;
            int nks = (rt < 26) ? 10 : 9;
            int kb0 = (ks * NKC) / nks, kb1 = ((ks + 1) * NKC) / nks;
            tc_unit(g_w2h, g_xpk, sB2, g_gpart[ks],
                    rt * 256, kb0, kb1, tid, wid);
        }
        gbarf(ep);

        // ---- P3: gates + c/h update + hs + packed h scatter ----
        {
            __syncthreads();
            if (tid < Bsz) s_tok[tid] = xb[(size_t)tid * Lseq + t];
            __syncthreads();
            float* hs = g_hsT + (size_t)t * HB;
            for (int i = gid; i < HB / 4; i += gstride) {
                int hj = i >> 4, b0 = (i & 15) * 4;
                float4 gv[4];
#pragma unroll
                for (int gg = 0; gg < 4; gg++) {
                    int r = gg * KP_GATE + hj;
                    float4 a;
                    a.x = g_gxtok[s_tok[b0]][gg * Hdim + hj];
                    a.y = g_gxtok[s_tok[b0 + 1]][gg * Hdim + hj];
                    a.z = g_gxtok[s_tok[b0 + 2]][gg * Hdim + hj];
                    a.w = g_gxtok[s_tok[b0 + 3]][gg * Hdim + hj];
#pragma unroll
                    for (int ks = 0; ks < 10; ks++) {
                        uint2 v = *(const uint2*)(g_gpart[ks] + (size_t)r * 64 + b0);
                        float2 f01 = unp2h(v.x), f23 = unp2h(v.y);
                        a.x += f01.x; a.y += f01.y; a.z += f23.x; a.w += f23.y;
                    }
                    gv[gg] = a;
                }
                float4 c4 = ((const float4*)g_cT)[i];
                float4 h4;
                const float* pi = (const float*)&gv[0];
                const float* pf = (const float*)&gv[1];
                const float* pg = (const float*)&gv[2];
                const float* po = (const float*)&gv[3];
                float* pc = (float*)&c4;
                float* ph = (float*)&h4;
#pragma unroll
                for (int q = 0; q < 4; q++) {
                    float si = __fdividef(1.f, 1.f + __expf(-pi[q]));
                    float sf = __fdividef(1.f, 1.f + __expf(-pf[q]));
                    float so = __fdividef(1.f, 1.f + __expf(-po[q]));
                    float c = sf * pc[q] + si * tanhf(pg[q]);
                    pc[q] = c;
                    float h = so * tanhf(c);
                    ph[q] = h;
                    g_hpk[bpk_idx(b0 + q, hj)] = f2h(h);
                }
                ((float4*)g_cT)[i] = c4;
                ((float4*)hs)[i] = h4;
            }
        }
        gbarf(ep);
    }
    gbar_final();

    // ================= final projection =================
    for (int unit = blockIdx.x; unit < Lseq; unit += gridDim.x) {
        const float* X = g_hsT + (size_t)unit * HB;
        float acc[4];
#pragma unroll
        for (int q = 0; q < 4; q++) acc[q] = 0.f;
        int b = tid & 63, ng = tid >> 6;   // ng 0..7
        for (int kt = 0; kt < 60; kt++) {
            int k0 = kt * 32;
            __syncthreads();
#pragma unroll
            for (int u = 0; u < 4; u++) {
                int idx = u * TPB + tid;
                int k = k0 + (idx >> 6);
                s_proj[idx] = (k < Hdim) ? X[(size_t)k0 * 64 + idx] : 0.f;
            }
            __syncthreads();
            int klim = Hdim - k0; if (klim > 32) klim = 32;
            for (int kk = 0; kk < klim; kk++) {
                float xv = s_proj[kk * 64 + b];
#pragma unroll
                for (int q = 0; q < 4; q++) {
                    int n = ng + q * 8;
                    if (n < NOUT) acc[q] = fmaf(xv, w_lin[(size_t)n * Hdim + k0 + kk], acc[q]);
                }
            }
        }
#pragma unroll
        for (int q = 0; q < 4; q++) {
            int n = ng + q * 8;
            if (n < NOUT)
                out[((size_t)b * Lseq + unit) * NOUT + n] = acc[q] + b_lin[n];
        }
    }
}

// ---------------- launcher: ONE graph node ----------------
extern "C" void kernel_launch(void* const* d_in, const int* in_sizes, int n_in,
                              void* d_out, int out_size)
{
    (void)in_sizes; (void)n_in; (void)out_size;
    const int*   xb    = (const int*)  d_in[0];
    // d_in[1] = xb_lens (unused by the reference math)
    const float* h0    = (const float*)d_in[2];
    const float* c0    = (const float*)d_in[3];
    const float* etab  = (const float*)d_in[4];
    const float* w_mx  = (const float*)d_in[5];
    const float* w_mh  = (const float*)d_in[6];
    const float* w_ih  = (const float*)d_in[7];
    const float* w_hm  = (const float*)d_in[8];
    const float* bias  = (const float*)d_in[9];
    const float* w_lin = (const float*)d_in[10];
    const float* b_lin = (const float*)d_in[11];
    float* out = (float*)d_out;

    static int smem_set = 0;
    if (!smem_set) {
        cudaFuncSetAttribute(uni_kernel, cudaFuncAttributeMaxDynamicSharedMemorySize, SMEM_BYTES);
        smem_set = 1;
    }

    int sms = 0;
    if (cudaDeviceGetAttribute(&sms, cudaDevAttrMultiProcessorCount, 0) != cudaSuccess || sms <= 0)
        sms = 148;

    uni_kernel<<<sms, TPB, SMEM_BYTES>>>(xb, h0, c0, etab, w_mx, w_mh, w_ih, w_hm,
                                         bias, w_lin, b_lin, out);
}